// round 11
// baseline (speedup 1.0000x reference)
#include <cuda_runtime.h>
#include <cuda_bf16.h>
#include <stdint.h>

// LegoConv2d GB300 — R10: mma.sync bf16 split-precision GEMM (compute_103-safe;
// tcgen05 is unusable because the harness emits plain compute_103 PTX).
// Persistent 152 CTAs (GB300 = 152 SMs) x 4 slabs each — zero quantization.
// Per slab (b,h): D[256 cols x 64 filters] = X^T[256 x 192] @ lego^T[192 x 64]
// via m16n8k16 bf16 with 3-term hi/lo compensation, fp32 accumulate.
// Fused argmax prep + one-hot gather epilogue, coalesced STG, no atomics.

#define NCTA   152
#define NSLABS 608
#define XS_K   52      // X_s row stride (bf16) — conflict-free A fragment LDS
#define LG_K   200     // lego_s row stride (bf16) — conflict-free B fragment LDS
#define FT_S   260     // feat row stride (f32) — conflict-free D dump

// smem byte offsets
#define SM_XH  0
#define SM_XL  (256*XS_K*2)            // 26624
#define SM_LH  (2*256*XS_K*2)          // 53248
#define SM_LL  (SM_LH + 64*LG_K*2)     // 78848
#define SM_FT  (SM_LL + 64*LG_K*2)     // 104448
#define SM_ID  (SM_FT + 64*FT_S*4)     // 171008
#define SM_CF  (SM_ID + 4096)          // 175104
#define SM_SZ  (SM_CF + 4096)          // 179200

__device__ __forceinline__ void mma_bf16(float* d, const uint32_t* a,
                                         uint32_t b0, uint32_t b1) {
    asm volatile(
        "mma.sync.aligned.m16n8k16.row.col.f32.bf16.bf16.f32 "
        "{%0,%1,%2,%3}, {%4,%5,%6,%7}, {%8,%9}, {%0,%1,%2,%3};"
        : "+f"(d[0]), "+f"(d[1]), "+f"(d[2]), "+f"(d[3])
        : "r"(a[0]), "r"(a[1]), "r"(a[2]), "r"(a[3]), "r"(b0), "r"(b1));
}

extern __shared__ char smem[];

__global__ __launch_bounds__(256, 1)
void main_kernel(const float* __restrict__ x,
                 const float* __restrict__ lego,
                 const float* __restrict__ coefs,
                 const float* __restrict__ comb,
                 float* __restrict__ out)
{
    const int t = threadIdx.x, lane = t & 31, wid = t >> 5;

    int*   idx_s  = (int*)(smem + SM_ID);
    float* coef_s = (float*)(smem + SM_CF);

    // ---- fused prep: warp-parallel first-max argmax + coefficient pick
    // row = i*256 + o (matches comb flatten (4,256,64)); 128 rows per warp.
    for (int row = wid * 128; row < wid * 128 + 128; row++) {
        float v = comb[(size_t)row * 64 + lane];
        int   i = lane;
        {
            float v2 = comb[(size_t)row * 64 + 32 + lane];
            if (v2 > v) { v = v2; i = lane + 32; }
        }
        #pragma unroll
        for (int off = 16; off; off >>= 1) {
            float ov = __shfl_xor_sync(0xFFFFFFFFu, v, off);
            int   oi = __shfl_xor_sync(0xFFFFFFFFu, i, off);
            if (ov > v || (ov == v && oi < i)) { v = ov; i = oi; }
        }
        if (lane == 0) {
            idx_s[row]  = i;
            coef_s[row] = coefs[(size_t)row * 64 + i];
        }
    }

    // ---- stage lego hi/lo once: lego_s[n][k], k contiguous (B col-major frags)
    {
        __nv_bfloat16* lh = (__nv_bfloat16*)(smem + SM_LH);
        __nv_bfloat16* ll = (__nv_bfloat16*)(smem + SM_LL);
        for (int s = t; s < 64 * 192; s += 256) {
            int n = s / 192, k = s - n * 192;
            float f = lego[s];
            __nv_bfloat16 hh = __float2bfloat16_rn(f);
            __nv_bfloat16 l2 = __float2bfloat16_rn(f - __bfloat162float(hh));
            lh[n * LG_K + k] = hh;
            ll[n * LG_K + k] = l2;
        }
    }
    __syncthreads();

    const int wm = wid & 3, wn = wid >> 2;      // warp grid 4(M) x 2(N)
    const int r  = lane >> 2, cq = lane & 3;

    const uint32_t* XH32 = (const uint32_t*)(smem + SM_XH);
    const uint32_t* XL32 = (const uint32_t*)(smem + SM_XL);
    const uint32_t* LH32 = (const uint32_t*)(smem + SM_LH);
    const uint32_t* LL32 = (const uint32_t*)(smem + SM_LL);
    float* feat = (float*)(smem + SM_FT);

    // staging role: thread t owns A row (merged col) t = i*64 + w
    const int  si = t >> 6, sw = t & 63;
    const bool valid = (sw < 56);

    for (int slab = blockIdx.x; slab < NSLABS; slab += NCTA) {
        const int h = slab % 19, b = slab / 19;

        float d[4][4][4];
        #pragma unroll
        for (int jm = 0; jm < 4; jm++)
            #pragma unroll
            for (int jn = 0; jn < 4; jn++)
                #pragma unroll
                for (int q = 0; q < 4; q++) d[jm][jn][q] = 0.f;

        for (int chunk = 0; chunk < 4; chunk++) {
            // ---- stage X chunk (16 channels x 3 taps = 48 k), hi/lo bf16
            {
                __nv_bfloat16* xh = (__nv_bfloat16*)(smem + SM_XH) + t * XS_K;
                __nv_bfloat16* xl = (__nv_bfloat16*)(smem + SM_XL) + t * XS_K;
                const float* xb = x +
                    ((size_t)(b * 256 + si * 64 + chunk * 16) * 56) * 56 + sw;
                #pragma unroll 4
                for (int c16 = 0; c16 < 16; c16++) {
                    const float* xr = xb + c16 * 3136;
                    float v[3];
                    if (valid) {
                        v[0] = (h > 0) ? xr[(3 * h - 1) * 56] : 0.f;
                        v[1] = xr[(3 * h) * 56];
                        v[2] = xr[(3 * h + 1) * 56];
                    } else { v[0] = v[1] = v[2] = 0.f; }
                    const int kk = c16 * 3;
                    #pragma unroll
                    for (int j = 0; j < 3; j++) {
                        __nv_bfloat16 hh = __float2bfloat16_rn(v[j]);
                        __nv_bfloat16 l2 =
                            __float2bfloat16_rn(v[j] - __bfloat162float(hh));
                        xh[kk + j] = hh;
                        xl[kk + j] = l2;
                    }
                }
            }
            __syncthreads();

            // ---- 3 k16-steps of mma over this chunk
            #pragma unroll
            for (int ks = 0; ks < 3; ks++) {
                const int ka = 8 * ks + cq;               // A u32 k-off (chunk-local)
                const int kb = chunk * 24 + 8 * ks + cq;  // B u32 k-off (global)

                uint32_t ah[4][4], al[4][4];
                #pragma unroll
                for (int jm = 0; jm < 4; jm++) {
                    const int base = (wm * 64 + 16 * jm + r) * (XS_K / 2) + ka;
                    ah[jm][0] = XH32[base];       ah[jm][1] = XH32[base + 8 * (XS_K / 2)];
                    ah[jm][2] = XH32[base + 4];   ah[jm][3] = XH32[base + 8 * (XS_K / 2) + 4];
                    al[jm][0] = XL32[base];       al[jm][1] = XL32[base + 8 * (XS_K / 2)];
                    al[jm][2] = XL32[base + 4];   al[jm][3] = XL32[base + 8 * (XS_K / 2) + 4];
                }
                #pragma unroll
                for (int jn = 0; jn < 4; jn++) {
                    const int nb = (wn * 32 + 8 * jn + r) * (LG_K / 2) + kb;
                    uint32_t bh0 = LH32[nb], bh1 = LH32[nb + 4];
                    uint32_t bl0 = LL32[nb], bl1 = LL32[nb + 4];
                    #pragma unroll
                    for (int jm = 0; jm < 4; jm++) {
                        mma_bf16(d[jm][jn], ah[jm], bh0, bh1);   // Ah*Bh
                        mma_bf16(d[jm][jn], al[jm], bh0, bh1);   // Al*Bh
                        mma_bf16(d[jm][jn], ah[jm], bl0, bl1);   // Ah*Bl
                    }
                }
            }
            __syncthreads();
        }

        // ---- dump D -> feat[n][m]  (m = merged col, n = filter)
        #pragma unroll
        for (int jm = 0; jm < 4; jm++)
            #pragma unroll
            for (int jn = 0; jn < 4; jn++) {
                const int m0 = wm * 64 + 16 * jm + r;
                const int n0 = wn * 32 + 8 * jn + 2 * cq;
                feat[n0 * FT_S + m0]           = d[jm][jn][0];
                feat[(n0 + 1) * FT_S + m0]     = d[jm][jn][1];
                feat[n0 * FT_S + m0 + 8]       = d[jm][jn][2];
                feat[(n0 + 1) * FT_S + m0 + 8] = d[jm][jn][3];
            }
        __syncthreads();

        // ---- epilogue: out[b,o,h,w+1] = sum_i coef[i,o]*feat[idx[i,o]][i*64+w]
        for (int s = t; s < 256 * 56; s += 256) {
            const int o = s / 56, w = s - o * 56;
            float acc = 0.f;
            #pragma unroll
            for (int i = 0; i < 4; i++) {
                const int   id = idx_s[i * 256 + o];
                const float cf = coef_s[i * 256 + o];
                acc = fmaf(cf, feat[id * FT_S + i * 64 + w], acc);
            }
            out[((size_t)(b * 256 + o) * 19 + h) * 58 + w + 1] = acc;
        }
        for (int s = t; s < 512; s += 256) {     // exact-zero borders w=0, w=57
            const int o = s >> 1, ww = (s & 1) ? 57 : 0;
            out[((size_t)(b * 256 + o) * 19 + h) * 58 + ww] = 0.f;
        }
        __syncthreads();   // feat fully read before next slab's dump
    }
}

extern "C" void kernel_launch(void* const* d_in, const int* in_sizes, int n_in,
                              void* d_out, int out_size) {
    const float* x     = (const float*)d_in[0];   // 32*256*56*56
    const float* lego  = (const float*)d_in[1];   // 64*64*3*1
    const float* coefs = (const float*)d_in[2];   // 4*256*64
    const float* comb  = (const float*)d_in[3];   // 4*256*64
    float* out = (float*)d_out;                   // 32*256*19*58
    (void)in_sizes; (void)n_in; (void)out_size;

    cudaFuncSetAttribute(main_kernel,
                         cudaFuncAttributeMaxDynamicSharedMemorySize, SM_SZ);
    main_kernel<<<NCTA, 256, SM_SZ>>>(x, lego, coefs, comb, out);
}

// round 12
// speedup vs baseline: 2.5327x; 2.5327x over previous
#include <cuda_runtime.h>
#include <cuda_bf16.h>
#include <stdint.h>

// LegoConv2d GB300 — R11: latency-hiding rework of the R10 mma.sync kernel.
// 512 thr / 16 warps, register-prefetched staging overlapped with MMA,
// double-buffered X (one sync per chunk), conflict-free strides throughout.
// Per slab (b,h): D[256 x 64] = X^T[256 x 192] @ lego^T[192 x 64],
// m16n8k16 bf16, 3-term hi/lo compensation, fp32 accumulate.

#define NCTA   152
#define NSLABS 608
#define XS_U   28      // X row stride in u32 (56 bf16) — perfect bank permutation
#define LG_U   100     // lego row stride in u32 (200 bf16) — conflict-free
#define FT_S   260     // feat row stride (f32) — conflict-free dump

// smem byte offsets
#define SM_XB0 0                         // buf0: hi 28672 | lo 28672
#define SM_XB1 57344
#define SM_LH  114688                    // 64*200*2 = 25600
#define SM_LL  140288
#define SM_ID  165888                    // int[1024]
#define SM_CF  169984                    // float[1024]
#define SM_SZ  174080
#define SM_FT  0                         // feat 64*260*4 = 66560, overlays X

__device__ __forceinline__ void mma_bf16(float* d, const uint32_t* a,
                                         uint32_t b0, uint32_t b1) {
    asm volatile(
        "mma.sync.aligned.m16n8k16.row.col.f32.bf16.bf16.f32 "
        "{%0,%1,%2,%3}, {%4,%5,%6,%7}, {%8,%9}, {%0,%1,%2,%3};"
        : "+f"(d[0]), "+f"(d[1]), "+f"(d[2]), "+f"(d[3])
        : "r"(a[0]), "r"(a[1]), "r"(a[2]), "r"(a[3]), "r"(b0), "r"(b1));
}
__device__ __forceinline__ uint32_t pk(__nv_bfloat16 a, __nv_bfloat16 b) {
    return (uint32_t)__bfloat16_as_ushort(a) | ((uint32_t)__bfloat16_as_ushort(b) << 16);
}

extern __shared__ char smem[];

__global__ __launch_bounds__(512, 1)
void main_kernel(const float* __restrict__ x,
                 const float* __restrict__ lego,
                 const float* __restrict__ coefs,
                 const float* __restrict__ comb,
                 float* __restrict__ out)
{
    const int t = threadIdx.x, lane = t & 31, wid = t >> 5;

    int*   idx_s  = (int*)(smem + SM_ID);
    float* coef_s = (float*)(smem + SM_CF);

    // ---- fused prep: warp-parallel first-max argmax + coefficient pick
    for (int row = wid * 64; row < wid * 64 + 64; row++) {
        float v = comb[(size_t)row * 64 + lane];
        int   i = lane;
        {
            float v2 = comb[(size_t)row * 64 + 32 + lane];
            if (v2 > v) { v = v2; i = lane + 32; }
        }
        #pragma unroll
        for (int off = 16; off; off >>= 1) {
            float ov = __shfl_xor_sync(0xFFFFFFFFu, v, off);
            int   oi = __shfl_xor_sync(0xFFFFFFFFu, i, off);
            if (ov > v || (ov == v && oi < i)) { v = ov; i = oi; }
        }
        if (lane == 0) {
            idx_s[row]  = i;
            coef_s[row] = coefs[(size_t)row * 64 + i];
        }
    }

    // ---- stage lego hi/lo once: lego_s[n][k], k contiguous
    {
        __nv_bfloat16* lh = (__nv_bfloat16*)(smem + SM_LH);
        __nv_bfloat16* ll = (__nv_bfloat16*)(smem + SM_LL);
        for (int s = t; s < 64 * 192; s += 512) {
            int n = s / 192, k = s - n * 192;
            float f = lego[s];
            __nv_bfloat16 hh = __float2bfloat16_rn(f);
            __nv_bfloat16 l2 = __float2bfloat16_rn(f - __bfloat162float(hh));
            lh[n * 2 * LG_U + k] = hh;
            ll[n * 2 * LG_U + k] = l2;
        }
    }
    __syncthreads();

    const int wm = wid & 3, wn = wid >> 2;      // warp grid 4(M) x 4(N)
    const int r  = lane >> 2, cq = lane & 3;

    const uint32_t* LH32 = (const uint32_t*)(smem + SM_LH);
    const uint32_t* LL32 = (const uint32_t*)(smem + SM_LL);
    float* feat = (float*)(smem + SM_FT);

    // staging role: thread owns A row (merged col) = t&255, k-half = t>>8
    const int  srow = t & 255, shalf = t >> 8;
    const int  si = srow >> 6, sw = srow & 63;
    const bool valid = (sw < 56);

    for (int slab = blockIdx.x; slab < NSLABS; slab += NCTA) {
        const int h = slab % 19, b = slab / 19;
        const int y0 = 3 * h - 1;

        float d[4][2][4];
        #pragma unroll
        for (int jm = 0; jm < 4; jm++)
            #pragma unroll
            for (int jn = 0; jn < 2; jn++)
                #pragma unroll
                for (int q = 0; q < 4; q++) d[jm][jn][q] = 0.f;

        // prefetch chunk 0 into regs: 8 channels x 3 taps
        float v[24];
        {
            const float* xb = x + ((size_t)(b * 256 + si * 64 + shalf * 8) * 56) * 56 + sw;
            #pragma unroll
            for (int j = 0; j < 8; j++) {
                const float* xr = xb + j * 3136;
                v[j * 3 + 0] = (valid && h > 0) ? xr[y0 * 56] : 0.f;
                v[j * 3 + 1] = valid ? xr[(y0 + 1) * 56] : 0.f;
                v[j * 3 + 2] = valid ? xr[(y0 + 2) * 56] : 0.f;
            }
        }

        for (int chunk = 0; chunk < 4; chunk++) {
            const int buf = chunk & 1;
            // ---- convert + pack + STS (3x STS.128 per hi/lo)
            {
                uint32_t ph[12], pl[12];
                #pragma unroll
                for (int m = 0; m < 12; m++) {
                    float f0 = v[2 * m], f1 = v[2 * m + 1];
                    __nv_bfloat16 h0 = __float2bfloat16_rn(f0);
                    __nv_bfloat16 h1 = __float2bfloat16_rn(f1);
                    ph[m] = pk(h0, h1);
                    pl[m] = pk(__float2bfloat16_rn(f0 - __bfloat162float(h0)),
                               __float2bfloat16_rn(f1 - __bfloat162float(h1)));
                }
                char* xh = smem + (buf ? SM_XB1 : SM_XB0) + srow * 112 + shalf * 48;
                char* xl = xh + 28672;
                #pragma unroll
                for (int q = 0; q < 3; q++) {
                    *(uint4*)(xh + q * 16) = *(uint4*)&ph[q * 4];
                    *(uint4*)(xl + q * 16) = *(uint4*)&pl[q * 4];
                }
            }
            __syncthreads();

            // ---- prefetch next chunk (LDG latency hidden by MMA below)
            if (chunk < 3) {
                const float* xb = x + ((size_t)(b * 256 + si * 64 +
                                   (chunk + 1) * 16 + shalf * 8) * 56) * 56 + sw;
                #pragma unroll
                for (int j = 0; j < 8; j++) {
                    const float* xr = xb + j * 3136;
                    v[j * 3 + 0] = (valid && h > 0) ? xr[y0 * 56] : 0.f;
                    v[j * 3 + 1] = valid ? xr[(y0 + 1) * 56] : 0.f;
                    v[j * 3 + 2] = valid ? xr[(y0 + 2) * 56] : 0.f;
                }
            }

            // ---- MMA over this chunk: 3 k16-steps
            const uint32_t* XH32 = (const uint32_t*)(smem + (buf ? SM_XB1 : SM_XB0));
            const uint32_t* XL32 = XH32 + 256 * XS_U;
            #pragma unroll
            for (int ks = 0; ks < 3; ks++) {
                const int ka = 8 * ks + cq;
                const int kb = chunk * 24 + 8 * ks + cq;
                uint32_t ah[4][4], al[4][4];
                #pragma unroll
                for (int jm = 0; jm < 4; jm++) {
                    const int base = (wm * 64 + 16 * jm + r) * XS_U + ka;
                    ah[jm][0] = XH32[base];            ah[jm][1] = XH32[base + 8 * XS_U];
                    ah[jm][2] = XH32[base + 4];        ah[jm][3] = XH32[base + 8 * XS_U + 4];
                    al[jm][0] = XL32[base];            al[jm][1] = XL32[base + 8 * XS_U];
                    al[jm][2] = XL32[base + 4];        al[jm][3] = XL32[base + 8 * XS_U + 4];
                }
                #pragma unroll
                for (int jn = 0; jn < 2; jn++) {
                    const int nb = (wn * 16 + 8 * jn + r) * LG_U + kb;
                    uint32_t bh0 = LH32[nb], bh1 = LH32[nb + 4];
                    uint32_t bl0 = LL32[nb], bl1 = LL32[nb + 4];
                    #pragma unroll
                    for (int jm = 0; jm < 4; jm++) {
                        mma_bf16(d[jm][jn], ah[jm], bh0, bh1);   // Ah*Bh
                        mma_bf16(d[jm][jn], al[jm], bh0, bh1);   // Al*Bh
                        mma_bf16(d[jm][jn], ah[jm], bl0, bl1);   // Ah*Bl
                    }
                }
            }
        }
        __syncthreads();   // all MMAs done (feat overlays X buffers)

        // ---- dump D -> feat[n][m]
        #pragma unroll
        for (int jm = 0; jm < 4; jm++)
            #pragma unroll
            for (int jn = 0; jn < 2; jn++) {
                const int m0 = wm * 64 + 16 * jm + r;
                const int n0 = wn * 16 + 8 * jn + 2 * cq;
                feat[n0 * FT_S + m0]           = d[jm][jn][0];
                feat[(n0 + 1) * FT_S + m0]     = d[jm][jn][1];
                feat[n0 * FT_S + m0 + 8]       = d[jm][jn][2];
                feat[(n0 + 1) * FT_S + m0 + 8] = d[jm][jn][3];
            }
        __syncthreads();

        // ---- epilogue: out[b,o,h,w+1] = sum_i coef[i,o]*feat[idx[i,o]][i*64+w]
        for (int s = t; s < 256 * 56; s += 512) {
            const int o = s / 56, w = s - o * 56;
            float acc = 0.f;
            #pragma unroll
            for (int i = 0; i < 4; i++) {
                const int   id = idx_s[i * 256 + o];
                const float cf = coef_s[i * 256 + o];
                acc = fmaf(cf, feat[id * FT_S + i * 64 + w], acc);
            }
            out[((size_t)(b * 256 + o) * 19 + h) * 58 + w + 1] = acc;
        }
        if (t < 512) {                           // exact-zero borders w=0, w=57
            const int o = t >> 1, ww = (t & 1) ? 57 : 0;
            out[((size_t)(b * 256 + o) * 19 + h) * 58 + ww] = 0.f;
        }
        __syncthreads();   // feat fully read before next slab's STS
    }
}

extern "C" void kernel_launch(void* const* d_in, const int* in_sizes, int n_in,
                              void* d_out, int out_size) {
    const float* x     = (const float*)d_in[0];   // 32*256*56*56
    const float* lego  = (const float*)d_in[1];   // 64*64*3*1
    const float* coefs = (const float*)d_in[2];   // 4*256*64
    const float* comb  = (const float*)d_in[3];   // 4*256*64
    float* out = (float*)d_out;                   // 32*256*19*58
    (void)in_sizes; (void)n_in; (void)out_size;

    cudaFuncSetAttribute(main_kernel,
                         cudaFuncAttributeMaxDynamicSharedMemorySize, SM_SZ);
    main_kernel<<<NCTA, 512, SM_SZ>>>(x, lego, coefs, comb, out);
}

// round 13
// speedup vs baseline: 2.7984x; 1.1049x over previous
#include <cuda_runtime.h>
#include <cuda_fp16.h>
#include <stdint.h>

// LegoConv2d GB300 — R12: pure-fp16 1-term mma.sync GEMM (rel err ~1e-4,
// 10x under budget), ldmatrix fragment loads, permuted K axis
// (k = chunk*48 + tap*16 + c16, same for A and B), 2 CTAs/SM (occ 50%).
// Per slab (b,h): feat[256 m x 64 n] = X^T fp16 @ lego fp16, fp32 accum.
// Grid 304 x exactly 2 slabs. Fused argmax prep + gather epilogue.

#define NCTA   304
#define NSLABS 608
#define FT_S   260            // feat row stride (f32), conflict-free dump

// smem byte offsets (per CTA, 100352 B total -> 2 CTAs/SM)
#define SM_XB0 0              // X buf0: 256 rows x 56 fp16 (stride 112B) = 28672
#define SM_XB1 28672
#define SM_LG  66560          // lego: 64 n x 200 fp16 (stride 400B) = 25600
#define SM_ID  92160          // int[1024]
#define SM_CF  96256          // float[1024]
#define SM_SZ  100352
// feat (f32 64 x FT_S = 66560 B) overlays both X buffers [0, 66560)

__device__ __forceinline__ uint32_t smem_u32(const void* p) {
    uint32_t a;
    asm("{ .reg .u64 t; cvta.to.shared.u64 t, %1; cvt.u32.u64 %0, t; }" : "=r"(a) : "l"(p));
    return a;
}
__device__ __forceinline__ void ldmx4(uint32_t* r, uint32_t addr) {
    asm volatile("ldmatrix.sync.aligned.m8n8.x4.shared.b16 {%0,%1,%2,%3}, [%4];"
                 : "=r"(r[0]), "=r"(r[1]), "=r"(r[2]), "=r"(r[3]) : "r"(addr));
}
__device__ __forceinline__ void mma_fp16(float* d, const uint32_t* a,
                                         uint32_t b0, uint32_t b1) {
    asm volatile(
        "mma.sync.aligned.m16n8k16.row.col.f32.f16.f16.f32 "
        "{%0,%1,%2,%3}, {%4,%5,%6,%7}, {%8,%9}, {%0,%1,%2,%3};"
        : "+f"(d[0]), "+f"(d[1]), "+f"(d[2]), "+f"(d[3])
        : "r"(a[0]), "r"(a[1]), "r"(a[2]), "r"(a[3]), "r"(b0), "r"(b1));
}
__device__ __forceinline__ uint32_t pkh2(float lo, float hi) {
    __half2 h = __floats2half2_rn(lo, hi);
    return *(uint32_t*)&h;
}

extern __shared__ char smem[];

__global__ __launch_bounds__(512, 2)
void main_kernel(const float* __restrict__ x,
                 const float* __restrict__ lego,
                 const float* __restrict__ coefs,
                 const float* __restrict__ comb,
                 float* __restrict__ out)
{
    const int t = threadIdx.x, lane = t & 31, wid = t >> 5;
    const uint32_t sb = smem_u32(smem);

    int*   idx_s  = (int*)(smem + SM_ID);
    float* coef_s = (float*)(smem + SM_CF);

    // ---- fused prep: warp-parallel first-max argmax + coefficient pick
    for (int row = wid * 64; row < wid * 64 + 64; row++) {
        float v = comb[(size_t)row * 64 + lane];
        int   i = lane;
        {
            float v2 = comb[(size_t)row * 64 + 32 + lane];
            if (v2 > v) { v = v2; i = lane + 32; }
        }
        #pragma unroll
        for (int off = 16; off; off >>= 1) {
            float ov = __shfl_xor_sync(0xFFFFFFFFu, v, off);
            int   oi = __shfl_xor_sync(0xFFFFFFFFu, i, off);
            if (ov > v || (ov == v && oi < i)) { v = ov; i = oi; }
        }
        if (lane == 0) {
            idx_s[row]  = i;
            coef_s[row] = coefs[(size_t)row * 64 + i];
        }
    }

    // ---- stage lego fp16 once, K-permuted: k = (c>>4)*48 + tap*16 + (c&15)
    {
        __half* lg = (__half*)(smem + SM_LG);
        for (int s = t; s < 64 * 192; s += 512) {
            int n = s / 192, r = s - n * 192, c = r / 3, tap = r - c * 3;
            int k = (c >> 4) * 48 + tap * 16 + (c & 15);
            lg[n * 200 + k] = __float2half_rn(lego[s]);
        }
    }
    __syncthreads();

    const int wm = wid & 3, wn = wid >> 2;      // warp grid 4(M) x 4(N)
    const int r  = lane >> 2, cq = lane & 3;

    // ldmatrix lane base addresses
    const uint32_t a_base = sb +
        (uint32_t)((wm * 64 + (lane & 15)) * 112 + (lane >> 4) * 16);
    const uint32_t b_base = sb + SM_LG +
        (uint32_t)((wn * 16 + 8 * ((lane >> 4) & 1) + (lane & 7)) * 400 +
                   16 * ((lane >> 3) & 1));

    float* feat = (float*)smem;

    // staging role: thread owns A row (merged col) = t&255, channel-half t>>8
    const int  srow = t & 255, shalf = t >> 8;
    const int  si = srow >> 6, sw = srow & 63;
    const bool valid = (sw < 56);
    char* xs_base = smem + srow * 112 + shalf * 16;   // + buf + tap*32

    for (int slab = blockIdx.x; slab < NSLABS; slab += NCTA) {
        const int h = slab % 19, b = slab / 19;
        const int y0 = 3 * h - 1;

        float d[4][2][4];
        #pragma unroll
        for (int jm = 0; jm < 4; jm++)
            #pragma unroll
            for (int jn = 0; jn < 2; jn++)
                #pragma unroll
                for (int q = 0; q < 4; q++) d[jm][jn][q] = 0.f;

        for (int chunk = 0; chunk < 4; chunk++) {
            const int buf = chunk & 1;

            // ---- stage X chunk: per tap, 8 channel planes -> one STS.128
            {
                const float* xb = x + ((size_t)(b * 256 + si * 64 +
                                    chunk * 16 + shalf * 8) * 56) * 56 + sw;
                char* xdst = xs_base + buf * 28672;
                #pragma unroll
                for (int tap = 0; tap < 3; tap++) {
                    const int y = y0 + tap;
                    float v[8];
                    if (valid && y >= 0) {
                        #pragma unroll
                        for (int j = 0; j < 8; j++) v[j] = xb[j * 3136 + y * 56];
                    } else {
                        #pragma unroll
                        for (int j = 0; j < 8; j++) v[j] = 0.f;
                    }
                    uint4 p;
                    p.x = pkh2(v[0], v[1]); p.y = pkh2(v[2], v[3]);
                    p.z = pkh2(v[4], v[5]); p.w = pkh2(v[6], v[7]);
                    *(uint4*)(xdst + tap * 32) = p;
                }
            }
            __syncthreads();

            // ---- MMA over chunk: 3 k16-steps (ks == tap in permuted K)
            #pragma unroll
            for (int ks = 0; ks < 3; ks++) {
                uint32_t bfr[4];
                ldmx4(bfr, b_base + chunk * 96 + ks * 32);
                #pragma unroll
                for (int jm = 0; jm < 4; jm++) {
                    uint32_t afr[4];
                    ldmx4(afr, a_base + buf * 28672 + jm * 1792 + ks * 32);
                    mma_fp16(d[jm][0], afr, bfr[0], bfr[1]);
                    mma_fp16(d[jm][1], afr, bfr[2], bfr[3]);
                }
            }
        }
        __syncthreads();   // all MMAs done; feat overlays X buffers

        // ---- dump D -> feat[n][m]
        #pragma unroll
        for (int jm = 0; jm < 4; jm++)
            #pragma unroll
            for (int jn = 0; jn < 2; jn++) {
                const int m0 = wm * 64 + 16 * jm + r;
                const int n0 = wn * 16 + 8 * jn + 2 * cq;
                feat[n0 * FT_S + m0]           = d[jm][jn][0];
                feat[(n0 + 1) * FT_S + m0]     = d[jm][jn][1];
                feat[n0 * FT_S + m0 + 8]       = d[jm][jn][2];
                feat[(n0 + 1) * FT_S + m0 + 8] = d[jm][jn][3];
            }
        __syncthreads();

        // ---- epilogue: out[b,o,h,w+1] = sum_i coef[i,o]*feat[idx[i,o]][i*64+w]
        {
            float* ob = out + ((size_t)(b * 256) * 19 + h) * 58;
            int o = t / 56, w = t - o * 56;
            #pragma unroll 4
            for (int it = 0; it < 28; it++) {
                float acc = 0.f;
                #pragma unroll
                for (int i = 0; i < 4; i++) {
                    const int   id = idx_s[i * 256 + o];
                    const float cf = coef_s[i * 256 + o];
                    acc = fmaf(cf, feat[id * FT_S + i * 64 + w], acc);
                }
                ob[o * 1102 + w + 1] = acc;
                o += 9; w += 8;
                if (w >= 56) { w -= 56; o += 1; }
            }
            // exact-zero borders w=0, w=57
            const int oo = t >> 1, ww = (t & 1) ? 57 : 0;
            ob[oo * 1102 + ww] = 0.f;
        }
        __syncthreads();   // feat fully read before next slab's STS
    }
}

extern "C" void kernel_launch(void* const* d_in, const int* in_sizes, int n_in,
                              void* d_out, int out_size) {
    const float* x     = (const float*)d_in[0];   // 32*256*56*56
    const float* lego  = (const float*)d_in[1];   // 64*64*3*1
    const float* coefs = (const float*)d_in[2];   // 4*256*64
    const float* comb  = (const float*)d_in[3];   // 4*256*64
    float* out = (float*)d_out;                   // 32*256*19*58
    (void)in_sizes; (void)n_in; (void)out_size;

    cudaFuncSetAttribute(main_kernel,
                         cudaFuncAttributeMaxDynamicSharedMemorySize, SM_SZ);
    main_kernel<<<NCTA, 512, SM_SZ>>>(x, lego, coefs, comb, out);
}